// round 8
// baseline (speedup 1.0000x reference)
#include <cuda_runtime.h>
#include <cstdint>

#define T_STEPS 128
#define CIN 16
#define H 64
#define W 64
#define CO 64
#define PLANE (H*W)            // 4096
#define FRAME (CO*PLANE)       // 262144
#define TOTAL (T_STEPS*FRAME)  // 33554432

// conv scratch (static __device__ array: allocation-free per harness rules)
__device__ float g_conv[TOTAL];

#define TILE_H 8
#define TILE_W 16
#define XS_H   (TILE_H + 2)    // 10
#define XS_WD  (TILE_W + 2)    // 18
#define XS_STRIDE 19           // odd stride -> spread banks
#define XS_ELEMS (CIN * XS_H * XS_WD)     // 2880
#define CO_PER_BLK 32
#define T_PER_BLK 2

// ---- packed f32x2 helpers (sm_103a FFMA2 path; only reachable via PTX) ----
__device__ __forceinline__ uint64_t pk2(float lo, float hi) {
    uint64_t r;
    asm("mov.b64 %0, {%1, %2};" : "=l"(r) : "f"(lo), "f"(hi));
    return r;
}
__device__ __forceinline__ void upk2(uint64_t v, float& lo, float& hi) {
    asm("mov.b64 {%0, %1}, %2;" : "=f"(lo), "=f"(hi) : "l"(v));
}
__device__ __forceinline__ uint64_t fma2(uint64_t a, uint64_t b, uint64_t c) {
    uint64_t r;
    asm("fma.rn.f32x2 %0, %1, %2, %3;" : "=l"(r) : "l"(a), "l"(b), "l"(c));
    return r;
}

// ---------------------------------------------------------------------------
// Conv kernel: grid (32 spatial tiles, 2 co-groups, 64 t-pairs), 128 threads.
// Processes TWO timesteps per block: weights loaded once, both halos loaded
// in one batched prologue (one barrier), then two compute passes.
// Thread computes 8 c_out x 4 w at one h; c_out packed in PAIRS (f32x2 acc).
// x: scalar floats in smem (proven path), packed (v,v) via MOV (ALU pipe).
// Weight pairs (c,c+1) contiguous in ws (co-fastest) -> warp-uniform LDS.64.
// ---------------------------------------------------------------------------
__global__ __launch_bounds__(128, 4)
void conv_kernel(const float* __restrict__ x, const float* __restrict__ Wt,
                 const float* __restrict__ b) {
    __shared__ float xs[T_PER_BLK][CIN * XS_H * XS_STRIDE]; // 2 x 12.2 KB
    __shared__ float ws[CIN * 9 * CO_PER_BLK];              // 18.4 KB

    const int tid  = threadIdx.x;
    const int t0   = blockIdx.z * T_PER_BLK;
    const int cog  = blockIdx.y;                   // co group (32 each)
    const int tile = blockIdx.x;                   // 0..31
    const int h0   = (tile >> 2) * TILE_H;
    const int w0   = (tile & 3) * TILE_W;
    const int co0  = cog * CO_PER_BLK;

    // Load weights: ws[(cin*9 + k)*32 + co_local]  (co fastest)
    #pragma unroll 4
    for (int i = tid; i < CIN * 9 * CO_PER_BLK; i += 128) {
        int col = i & 31;          // co local
        int k9  = i >> 5;          // cin*9 + kh*3 + kw
        ws[i] = Wt[(co0 + col) * (CIN * 9) + k9];
    }

    // Load BOTH halo tiles with zero padding (batched: high MLP)
    #pragma unroll 4
    for (int i = tid; i < T_PER_BLK * XS_ELEMS; i += 128) {
        int tt  = i / XS_ELEMS;
        int e   = i - tt * XS_ELEMS;
        int c   = e % XS_WD;
        int rc  = e / XS_WD;
        int r   = rc % XS_H;
        int cin = rc / XS_H;
        int y   = h0 - 1 + r;
        int xg  = w0 - 1 + c;
        float v = 0.0f;
        if ((unsigned)y < (unsigned)H && (unsigned)xg < (unsigned)W)
            v = x[(size_t)(t0 + tt) * (CIN * PLANE) + cin * PLANE + y * W + xg];
        xs[tt][cin * (XS_H * XS_STRIDE) + r * XS_STRIDE + c] = v;
    }
    __syncthreads();

    const int co_sub = tid >> 5;            // 0..3  (uniform within warp)
    const int lane   = tid & 31;
    const int hl     = lane >> 2;           // 0..7
    const int wl     = (lane & 3) * 4;      // 0,4,8,12
    const int co_b   = co_sub * 8;          // local co base (8 c_out / thread)

    // bias pairs (reused for both timesteps)
    uint64_t bp[4];
    #pragma unroll
    for (int p = 0; p < 4; p++)
        bp[p] = pk2(b[co0 + co_b + 2 * p], b[co0 + co_b + 2 * p + 1]);

    #pragma unroll
    for (int tt = 0; tt < T_PER_BLK; tt++) {
        // acc[p][w] packs c_out pair (co_b+2p, co_b+2p+1) at output column w
        uint64_t acc[4][4];
        #pragma unroll
        for (int p = 0; p < 4; p++)
            #pragma unroll
            for (int w = 0; w < 4; w++) acc[p][w] = bp[p];

        #pragma unroll
        for (int cin = 0; cin < CIN; cin++) {
            #pragma unroll
            for (int kh = 0; kh < 3; kh++) {
                const float* row =
                    &xs[tt][cin * (XS_H * XS_STRIDE) + (hl + kh) * XS_STRIDE + wl];
                uint64_t xx[6];
                #pragma unroll
                for (int j = 0; j < 6; j++) {
                    float xv = row[j];
                    xx[j] = pk2(xv, xv);
                }
                const float* wp = &ws[(cin * 9 + kh * 3) * CO_PER_BLK + co_b];
                #pragma unroll
                for (int p = 0; p < 4; p++) {
                    // contiguous c-pairs -> aligned 8B warp-uniform broadcasts
                    uint64_t wk0 = *(const uint64_t*)(wp + 2 * p);
                    uint64_t wk1 = *(const uint64_t*)(wp + CO_PER_BLK + 2 * p);
                    uint64_t wk2 = *(const uint64_t*)(wp + 2 * CO_PER_BLK + 2 * p);
                    #pragma unroll
                    for (int w = 0; w < 4; w++) {
                        acc[p][w] = fma2(xx[w],     wk0, acc[p][w]);
                        acc[p][w] = fma2(xx[w + 1], wk1, acc[p][w]);
                        acc[p][w] = fma2(xx[w + 2], wk2, acc[p][w]);
                    }
                }
            }
        }

        // Unpack and store: one float4 per c_out (w-contiguous, 16B aligned)
        #pragma unroll
        for (int p = 0; p < 4; p++) {
            float lo[4], hi[4];
            #pragma unroll
            for (int w = 0; w < 4; w++) upk2(acc[p][w], lo[w], hi[w]);
            int co_e = co0 + co_b + 2 * p;
            size_t base = (size_t)(t0 + tt) * FRAME + (h0 + hl) * W + (w0 + wl);
            *(float4*)&g_conv[base + (size_t)co_e * PLANE] =
                make_float4(lo[0], lo[1], lo[2], lo[3]);
            *(float4*)&g_conv[base + (size_t)(co_e + 1) * PLANE] =
                make_float4(hi[0], hi[1], hi[2], hi[3]);
        }
    }
}

// ---------------------------------------------------------------------------
// Scan kernel: one thread per (c_out,h,w); sequential LIF over T.
// Proven best form: 256 threads, scalar coalesced loads (38.6us, 70% DRAM).
// ---------------------------------------------------------------------------
__global__ __launch_bounds__(256)
void scan_kernel(float* __restrict__ out) {
    const int idx = blockIdx.x * 256 + threadIdx.x;   // < FRAME
    const float* cp = g_conv + idx;
    float* op = out + idx;
    float state = 0.0f;
    #pragma unroll 8
    for (int t = 0; t < T_STEPS; t++) {
        float v = cp[(size_t)t * FRAME];
        state += v;
        float spike = (state >= 8.0f) ? 1.0f : 0.0f;      // fire
        state = (state >= 8.0f) ? 0.0f : state;           // reset-to-value 0
        state = (state > -1.0f) ? state : -1.0f;          // Threshold(-1,-1)
        op[(size_t)t * FRAME] = spike;
    }
}

extern "C" void kernel_launch(void* const* d_in, const int* in_sizes, int n_in,
                              void* d_out, int out_size) {
    // Identify inputs by unique element counts (robust to ordering)
    const float* x  = nullptr;
    const float* Wt = nullptr;
    const float* b  = nullptr;
    for (int i = 0; i < n_in; i++) {
        if (in_sizes[i] == T_STEPS * CIN * PLANE) x  = (const float*)d_in[i];
        else if (in_sizes[i] == CO * CIN * 9)     Wt = (const float*)d_in[i];
        else if (in_sizes[i] == CO)               b  = (const float*)d_in[i];
    }
    float* out = (float*)d_out;

    dim3 grid(32, 2, T_STEPS / T_PER_BLK);      // 32 x 2 x 64 = 4096 blocks
    conv_kernel<<<grid, 128>>>(x, Wt, b);
    scan_kernel<<<FRAME / 256, 256>>>(out);
}

// round 10
// speedup vs baseline: 2.9308x; 2.9308x over previous
#include <cuda_runtime.h>
#include <cstdint>

#define T_STEPS 128
#define CIN 16
#define H 64
#define W 64
#define CO 64
#define PLANE (H*W)            // 4096
#define FRAME (CO*PLANE)       // 262144
#define TOTAL (T_STEPS*FRAME)  // 33554432

// conv scratch (static __device__ array: allocation-free per harness rules)
__device__ float g_conv[TOTAL];

#define TILE_H 8
#define TILE_W 16
#define XS_H   (TILE_H + 2)    // 10
#define XS_WD  (TILE_W + 2)    // 18
#define XS_STRIDE 19           // odd stride -> spread banks
#define XS_ELEMS (CIN * XS_H * XS_WD)     // 2880
#define CO_PER_BLK 32
#define T_PER_BLK 4

// ---- packed f32x2 helpers (sm_103a FFMA2 path; only reachable via PTX) ----
__device__ __forceinline__ uint64_t pk2(float lo, float hi) {
    uint64_t r;
    asm("mov.b64 %0, {%1, %2};" : "=l"(r) : "f"(lo), "f"(hi));
    return r;
}
__device__ __forceinline__ void upk2(uint64_t v, float& lo, float& hi) {
    asm("mov.b64 {%0, %1}, %2;" : "=f"(lo), "=f"(hi) : "l"(v));
}
__device__ __forceinline__ uint64_t fma2(uint64_t a, uint64_t b, uint64_t c) {
    uint64_t r;
    asm("fma.rn.f32x2 %0, %1, %2, %3;" : "=l"(r) : "l"(a), "l"(b), "l"(c));
    return r;
}

// ---------------------------------------------------------------------------
// Conv kernel: grid (32 spatial tiles, 2 co-groups, 32 t-quads), 128 threads.
// EXACT R5 per-timestep structure (smem 30.6KB, occ 5, same inner loop),
// but each block processes 4 timesteps sequentially, REUSING the same xs
// halo buffer (#pragma unroll 1: no body duplication, no smem growth).
// Weights loaded ONCE per block -> per-t prologue drops 58 -> ~23 loads/thr.
// Thread computes 8 c_out x 4 w at one h; c_out packed in PAIRS (f32x2 acc).
// x: scalar floats in smem, packed (v,v) via MOV (ALU pipe, overlaps FMA).
// Weight pairs (c,c+1) contiguous in ws (co-fastest) -> warp-uniform LDS.64.
// ---------------------------------------------------------------------------
__global__ __launch_bounds__(128, 5)
void conv_kernel(const float* __restrict__ x, const float* __restrict__ Wt,
                 const float* __restrict__ b) {
    __shared__ float xs[CIN * XS_H * XS_STRIDE];   // 3040 f = 12.2 KB
    __shared__ float ws[CIN * 9 * CO_PER_BLK];     // 4608 f = 18.4 KB

    const int tid  = threadIdx.x;
    const int t0   = blockIdx.z * T_PER_BLK;
    const int cog  = blockIdx.y;                   // co group (32 each)
    const int tile = blockIdx.x;                   // 0..31
    const int h0   = (tile >> 2) * TILE_H;
    const int w0   = (tile & 3) * TILE_W;
    const int co0  = cog * CO_PER_BLK;

    // Load weights ONCE: ws[(cin*9 + k)*32 + co_local]  (co fastest)
    #pragma unroll 4
    for (int i = tid; i < CIN * 9 * CO_PER_BLK; i += 128) {
        int col = i & 31;          // co local
        int k9  = i >> 5;          // cin*9 + kh*3 + kw
        ws[i] = Wt[(co0 + col) * (CIN * 9) + k9];
    }

    const int co_sub = tid >> 5;            // 0..3  (uniform within warp)
    const int lane   = tid & 31;
    const int hl     = lane >> 2;           // 0..7
    const int wl     = (lane & 3) * 4;      // 0,4,8,12
    const int co_b   = co_sub * 8;          // local co base (8 c_out / thread)

    // bias pairs (reused across timesteps)
    uint64_t bp[4];
    #pragma unroll
    for (int p = 0; p < 4; p++)
        bp[p] = pk2(b[co0 + co_b + 2 * p], b[co0 + co_b + 2 * p + 1]);

    #pragma unroll 1
    for (int tq = 0; tq < T_PER_BLK; tq++) {
        const int t = t0 + tq;

        // barrier: previous compute done reading xs (also orders ws on tq=0)
        __syncthreads();

        // Load x halo tile for this t with zero padding (scalar floats)
        const float* xt = x + (size_t)t * (CIN * PLANE);
        #pragma unroll 4
        for (int i = tid; i < XS_ELEMS; i += 128) {
            int c   = i % XS_WD;
            int rc  = i / XS_WD;
            int r   = rc % XS_H;
            int cin = rc / XS_H;
            int y   = h0 - 1 + r;
            int xg  = w0 - 1 + c;
            float v = 0.0f;
            if ((unsigned)y < (unsigned)H && (unsigned)xg < (unsigned)W)
                v = xt[cin * PLANE + y * W + xg];
            xs[cin * (XS_H * XS_STRIDE) + r * XS_STRIDE + c] = v;
        }
        __syncthreads();

        // acc[p][w] packs c_out pair (co_b+2p, co_b+2p+1) at output column w
        uint64_t acc[4][4];
        #pragma unroll
        for (int p = 0; p < 4; p++)
            #pragma unroll
            for (int w = 0; w < 4; w++) acc[p][w] = bp[p];

        #pragma unroll
        for (int cin = 0; cin < CIN; cin++) {
            #pragma unroll
            for (int kh = 0; kh < 3; kh++) {
                const float* row =
                    &xs[cin * (XS_H * XS_STRIDE) + (hl + kh) * XS_STRIDE + wl];
                uint64_t xx[6];
                #pragma unroll
                for (int j = 0; j < 6; j++) {
                    float xv = row[j];
                    xx[j] = pk2(xv, xv);
                }
                const float* wp = &ws[(cin * 9 + kh * 3) * CO_PER_BLK + co_b];
                #pragma unroll
                for (int p = 0; p < 4; p++) {
                    // contiguous c-pairs -> aligned 8B warp-uniform broadcasts
                    uint64_t wk0 = *(const uint64_t*)(wp + 2 * p);
                    uint64_t wk1 = *(const uint64_t*)(wp + CO_PER_BLK + 2 * p);
                    uint64_t wk2 = *(const uint64_t*)(wp + 2 * CO_PER_BLK + 2 * p);
                    #pragma unroll
                    for (int w = 0; w < 4; w++) {
                        acc[p][w] = fma2(xx[w],     wk0, acc[p][w]);
                        acc[p][w] = fma2(xx[w + 1], wk1, acc[p][w]);
                        acc[p][w] = fma2(xx[w + 2], wk2, acc[p][w]);
                    }
                }
            }
        }

        // Unpack and store: one float4 per c_out (w-contiguous, 16B aligned)
        #pragma unroll
        for (int p = 0; p < 4; p++) {
            float lo[4], hi[4];
            #pragma unroll
            for (int w = 0; w < 4; w++) upk2(acc[p][w], lo[w], hi[w]);
            int co_e = co0 + co_b + 2 * p;
            size_t base = (size_t)t * FRAME + (h0 + hl) * W + (w0 + wl);
            *(float4*)&g_conv[base + (size_t)co_e * PLANE] =
                make_float4(lo[0], lo[1], lo[2], lo[3]);
            *(float4*)&g_conv[base + (size_t)(co_e + 1) * PLANE] =
                make_float4(hi[0], hi[1], hi[2], hi[3]);
        }
    }
}

// ---------------------------------------------------------------------------
// Scan kernel: one thread per (c_out,h,w); sequential LIF over T.
// Proven best form: 256 threads, scalar coalesced loads (38.6us, 70% DRAM).
// ---------------------------------------------------------------------------
__global__ __launch_bounds__(256)
void scan_kernel(float* __restrict__ out) {
    const int idx = blockIdx.x * 256 + threadIdx.x;   // < FRAME
    const float* cp = g_conv + idx;
    float* op = out + idx;
    float state = 0.0f;
    #pragma unroll 8
    for (int t = 0; t < T_STEPS; t++) {
        float v = cp[(size_t)t * FRAME];
        state += v;
        float spike = (state >= 8.0f) ? 1.0f : 0.0f;      // fire
        state = (state >= 8.0f) ? 0.0f : state;           // reset-to-value 0
        state = (state > -1.0f) ? state : -1.0f;          // Threshold(-1,-1)
        op[(size_t)t * FRAME] = spike;
    }
}

extern "C" void kernel_launch(void* const* d_in, const int* in_sizes, int n_in,
                              void* d_out, int out_size) {
    // Identify inputs by unique element counts (robust to ordering)
    const float* x  = nullptr;
    const float* Wt = nullptr;
    const float* b  = nullptr;
    for (int i = 0; i < n_in; i++) {
        if (in_sizes[i] == T_STEPS * CIN * PLANE) x  = (const float*)d_in[i];
        else if (in_sizes[i] == CO * CIN * 9)     Wt = (const float*)d_in[i];
        else if (in_sizes[i] == CO)               b  = (const float*)d_in[i];
    }
    float* out = (float*)d_out;

    dim3 grid(32, 2, T_STEPS / T_PER_BLK);      // 32 x 2 x 32 = 2048 blocks
    conv_kernel<<<grid, 128>>>(x, Wt, b);
    scan_kernel<<<FRAME / 256, 256>>>(out);
}

// round 12
// speedup vs baseline: 2.9727x; 1.0143x over previous
#include <cuda_runtime.h>
#include <cstdint>

#define T_STEPS 128
#define CIN 16
#define H 64
#define W 64
#define CO 64
#define PLANE (H*W)            // 4096
#define FRAME (CO*PLANE)       // 262144
#define TOTAL (T_STEPS*FRAME)  // 33554432

// conv scratch (static __device__ array: allocation-free per harness rules)
__device__ float g_conv[TOTAL];

#define TILE_H 8
#define TILE_W 16
#define XS_H   (TILE_H + 2)    // 10
#define XS_WD  (TILE_W + 2)    // 18
#define XS_STRIDE 19           // odd stride -> spread banks
#define XS_ELEMS (CIN * XS_H * XS_WD)     // 2880
#define CO_PER_BLK 32
#define T_PER_BLK 4

// ---- packed f32x2 helpers (sm_103a FFMA2 path; only reachable via PTX) ----
__device__ __forceinline__ uint64_t pk2(float lo, float hi) {
    uint64_t r;
    asm("mov.b64 %0, {%1, %2};" : "=l"(r) : "f"(lo), "f"(hi));
    return r;
}
__device__ __forceinline__ void upk2(uint64_t v, float& lo, float& hi) {
    asm("mov.b64 {%0, %1}, %2;" : "=f"(lo), "=f"(hi) : "l"(v));
}
__device__ __forceinline__ uint64_t fma2(uint64_t a, uint64_t b, uint64_t c) {
    uint64_t r;
    asm("fma.rn.f32x2 %0, %1, %2, %3;" : "=l"(r) : "l"(a), "l"(b), "l"(c));
    return r;
}

// ---- cp.async helpers: 4B copy with zero-fill when OOB (src-size form) ----
__device__ __forceinline__ void cp_async4(uint32_t dst_smem, const void* src,
                                          bool valid) {
    int sz = valid ? 4 : 0;
    asm volatile("cp.async.ca.shared.global [%0], [%1], 4, %2;"
                 :: "r"(dst_smem), "l"(src), "r"(sz));
}
__device__ __forceinline__ void cp_async_commit() {
    asm volatile("cp.async.commit_group;");
}
__device__ __forceinline__ void cp_async_wait_all() {
    asm volatile("cp.async.wait_group 0;");
}

// ---------------------------------------------------------------------------
// Conv kernel: grid (32 spatial tiles, 2 co-groups, 32 t-quads), 128 threads.
// R10 structure (T_PER_BLK=4, weights loaded once) + DOUBLE-BUFFERED halo:
// cp.async copies halo t+1 into the idle xs buffer while compute runs on the
// current one -> per-t halo latency fully hidden, one barrier per timestep.
// Thread computes 8 c_out x 4 w at one h; c_out packed in PAIRS (f32x2 acc).
// x: scalar floats in smem, packed (v,v) via MOV (ALU pipe, overlaps FMA).
// Weight pairs (c,c+1) contiguous in ws (co-fastest) -> warp-uniform LDS.64.
// ---------------------------------------------------------------------------
__global__ __launch_bounds__(128, 5)
void conv_kernel(const float* __restrict__ x, const float* __restrict__ Wt,
                 const float* __restrict__ b) {
    __shared__ float xs[2][CIN * XS_H * XS_STRIDE];  // 2 x 12.2 KB
    __shared__ float ws[CIN * 9 * CO_PER_BLK];       // 18.4 KB  (42.8 total)

    const int tid  = threadIdx.x;
    const int t0   = blockIdx.z * T_PER_BLK;
    const int cog  = blockIdx.y;                   // co group (32 each)
    const int tile = blockIdx.x;                   // 0..31
    const int h0   = (tile >> 2) * TILE_H;
    const int w0   = (tile & 3) * TILE_W;
    const int co0  = cog * CO_PER_BLK;

    // Load weights ONCE: ws[(cin*9 + k)*32 + co_local]  (co fastest)
    #pragma unroll 4
    for (int i = tid; i < CIN * 9 * CO_PER_BLK; i += 128) {
        int col = i & 31;          // co local
        int k9  = i >> 5;          // cin*9 + kh*3 + kw
        ws[i] = Wt[(co0 + col) * (CIN * 9) + k9];
    }

    // Async halo fill for timestep t into buffer buf
    auto fill_halo = [&](int t, int buf) {
        const float* xt = x + (size_t)t * (CIN * PLANE);
        #pragma unroll 4
        for (int i = tid; i < XS_ELEMS; i += 128) {
            int c   = i % XS_WD;
            int rc  = i / XS_WD;
            int r   = rc % XS_H;
            int cin = rc / XS_H;
            int y   = h0 - 1 + r;
            int xg  = w0 - 1 + c;
            bool ok = ((unsigned)y < (unsigned)H) & ((unsigned)xg < (unsigned)W);
            const float* src = ok ? &xt[cin * PLANE + y * W + xg] : xt;
            uint32_t dst = (uint32_t)__cvta_generic_to_shared(
                &xs[buf][cin * (XS_H * XS_STRIDE) + r * XS_STRIDE + c]);
            cp_async4(dst, src, ok);
        }
        cp_async_commit();
    };

    // Prologue: halo for t0 into buffer 0
    fill_halo(t0, 0);

    const int co_sub = tid >> 5;            // 0..3  (uniform within warp)
    const int lane   = tid & 31;
    const int hl     = lane >> 2;           // 0..7
    const int wl     = (lane & 3) * 4;      // 0,4,8,12
    const int co_b   = co_sub * 8;          // local co base (8 c_out / thread)

    // bias pairs (reused across timesteps)
    uint64_t bp[4];
    #pragma unroll
    for (int p = 0; p < 4; p++)
        bp[p] = pk2(b[co0 + co_b + 2 * p], b[co0 + co_b + 2 * p + 1]);

    cp_async_wait_all();
    __syncthreads();

    #pragma unroll 1
    for (int tq = 0; tq < T_PER_BLK; tq++) {
        const int t   = t0 + tq;
        const int buf = tq & 1;

        // Prefetch next halo into idle buffer (async; overlaps compute)
        if (tq + 1 < T_PER_BLK) fill_halo(t + 1, 1 - buf);

        // acc[p][w] packs c_out pair (co_b+2p, co_b+2p+1) at output column w
        uint64_t acc[4][4];
        #pragma unroll
        for (int p = 0; p < 4; p++)
            #pragma unroll
            for (int w = 0; w < 4; w++) acc[p][w] = bp[p];

        #pragma unroll
        for (int cin = 0; cin < CIN; cin++) {
            #pragma unroll
            for (int kh = 0; kh < 3; kh++) {
                const float* row =
                    &xs[buf][cin * (XS_H * XS_STRIDE) + (hl + kh) * XS_STRIDE + wl];
                uint64_t xx[6];
                #pragma unroll
                for (int j = 0; j < 6; j++) {
                    float xv = row[j];
                    xx[j] = pk2(xv, xv);
                }
                const float* wp = &ws[(cin * 9 + kh * 3) * CO_PER_BLK + co_b];
                #pragma unroll
                for (int p = 0; p < 4; p++) {
                    // contiguous c-pairs -> aligned 8B warp-uniform broadcasts
                    uint64_t wk0 = *(const uint64_t*)(wp + 2 * p);
                    uint64_t wk1 = *(const uint64_t*)(wp + CO_PER_BLK + 2 * p);
                    uint64_t wk2 = *(const uint64_t*)(wp + 2 * CO_PER_BLK + 2 * p);
                    #pragma unroll
                    for (int w = 0; w < 4; w++) {
                        acc[p][w] = fma2(xx[w],     wk0, acc[p][w]);
                        acc[p][w] = fma2(xx[w + 1], wk1, acc[p][w]);
                        acc[p][w] = fma2(xx[w + 2], wk2, acc[p][w]);
                    }
                }
            }
        }

        // Unpack and store: one float4 per c_out (w-contiguous, 16B aligned)
        #pragma unroll
        for (int p = 0; p < 4; p++) {
            float lo[4], hi[4];
            #pragma unroll
            for (int w = 0; w < 4; w++) upk2(acc[p][w], lo[w], hi[w]);
            int co_e = co0 + co_b + 2 * p;
            size_t base = (size_t)t * FRAME + (h0 + hl) * W + (w0 + wl);
            *(float4*)&g_conv[base + (size_t)co_e * PLANE] =
                make_float4(lo[0], lo[1], lo[2], lo[3]);
            *(float4*)&g_conv[base + (size_t)(co_e + 1) * PLANE] =
                make_float4(hi[0], hi[1], hi[2], hi[3]);
        }

        // Next buffer complete + everyone done reading current buffer
        cp_async_wait_all();
        __syncthreads();
    }
}

// ---------------------------------------------------------------------------
// Scan kernel: one thread per (c_out,h,w); sequential LIF over T.
// Proven best form: 256 threads, scalar coalesced loads (~39us, 70% DRAM).
// ---------------------------------------------------------------------------
__global__ __launch_bounds__(256)
void scan_kernel(float* __restrict__ out) {
    const int idx = blockIdx.x * 256 + threadIdx.x;   // < FRAME
    const float* cp = g_conv + idx;
    float* op = out + idx;
    float state = 0.0f;
    #pragma unroll 8
    for (int t = 0; t < T_STEPS; t++) {
        float v = cp[(size_t)t * FRAME];
        state += v;
        float spike = (state >= 8.0f) ? 1.0f : 0.0f;      // fire
        state = (state >= 8.0f) ? 0.0f : state;           // reset-to-value 0
        state = (state > -1.0f) ? state : -1.0f;          // Threshold(-1,-1)
        op[(size_t)t * FRAME] = spike;
    }
}

extern "C" void kernel_launch(void* const* d_in, const int* in_sizes, int n_in,
                              void* d_out, int out_size) {
    // Identify inputs by unique element counts (robust to ordering)
    const float* x  = nullptr;
    const float* Wt = nullptr;
    const float* b  = nullptr;
    for (int i = 0; i < n_in; i++) {
        if (in_sizes[i] == T_STEPS * CIN * PLANE) x  = (const float*)d_in[i];
        else if (in_sizes[i] == CO * CIN * 9)     Wt = (const float*)d_in[i];
        else if (in_sizes[i] == CO)               b  = (const float*)d_in[i];
    }
    float* out = (float*)d_out;

    dim3 grid(32, 2, T_STEPS / T_PER_BLK);      // 32 x 2 x 32 = 2048 blocks
    conv_kernel<<<grid, 128>>>(x, Wt, b);
    scan_kernel<<<FRAME / 256, 256>>>(out);
}

// round 15
// speedup vs baseline: 2.9777x; 1.0017x over previous
#include <cuda_runtime.h>
#include <cstdint>

#define T_STEPS 128
#define CIN 16
#define H 64
#define W 64
#define CO 64
#define PLANE (H*W)            // 4096
#define FRAME (CO*PLANE)       // 262144
#define TOTAL (T_STEPS*FRAME)  // 33554432

// conv scratch (static __device__ array: allocation-free per harness rules)
__device__ float g_conv[TOTAL];

#define TILE_H 8
#define TILE_W 16
#define XS_H   (TILE_H + 2)    // 10
#define XS_WD  (TILE_W + 2)    // 18
#define XS_STRIDE 19           // odd stride -> spread banks
#define XS_ELEMS (CIN * XS_H * XS_WD)     // 2880
#define CO_PER_BLK 32
#define T_PER_BLK 4

// ---- packed f32x2 helpers (sm_103a FFMA2 path; only reachable via PTX) ----
__device__ __forceinline__ uint64_t pk2(float lo, float hi) {
    uint64_t r;
    asm("mov.b64 %0, {%1, %2};" : "=l"(r) : "f"(lo), "f"(hi));
    return r;
}
__device__ __forceinline__ void upk2(uint64_t v, float& lo, float& hi) {
    asm("mov.b64 {%0, %1}, %2;" : "=f"(lo), "=f"(hi) : "l"(v));
}
__device__ __forceinline__ uint64_t fma2(uint64_t a, uint64_t b, uint64_t c) {
    uint64_t r;
    asm("fma.rn.f32x2 %0, %1, %2, %3;" : "=l"(r) : "l"(a), "l"(b), "l"(c));
    return r;
}

// ---- cp.async helpers: 4B copy with zero-fill when OOB (src-size form) ----
__device__ __forceinline__ void cp_async4(uint32_t dst_smem, const void* src,
                                          bool valid) {
    int sz = valid ? 4 : 0;
    asm volatile("cp.async.ca.shared.global [%0], [%1], 4, %2;"
                 :: "r"(dst_smem), "l"(src), "r"(sz));
}
__device__ __forceinline__ void cp_async_commit() {
    asm volatile("cp.async.commit_group;");
}
__device__ __forceinline__ void cp_async_wait_all() {
    asm volatile("cp.async.wait_group 0;");
}

// ---------------------------------------------------------------------------
// Conv kernel: grid (32 spatial tiles, 2 co-groups, 32 t-quads), 128 threads.
// Proven 268.7us structure (T_PER_BLK=4, cp.async double-buffered halo,
// weights loaded once) with two inner-loop changes:
//  (1) FFMA2s grouped kw-outer/w-inner so 4 consecutive FFMA2 share the same
//      weight b-operand (operand-reuse-latch friendly; neutral otherwise).
//  (2) Weight pairs loaded 4-at-a-time via LDS.128 (2 per kw vs 4 LDS.64).
// Thread computes 8 c_out x 4 w at one h; c_out packed in PAIRS (f32x2 acc).
// ---------------------------------------------------------------------------
__global__ __launch_bounds__(128, 5)
void conv_kernel(const float* __restrict__ x, const float* __restrict__ Wt,
                 const float* __restrict__ b) {
    __shared__ float xs[2][CIN * XS_H * XS_STRIDE];              // 2 x 12.2 KB
    __shared__ __align__(16) float ws[CIN * 9 * CO_PER_BLK];     // 18.4 KB

    const int tid  = threadIdx.x;
    const int t0   = blockIdx.z * T_PER_BLK;
    const int cog  = blockIdx.y;                   // co group (32 each)
    const int tile = blockIdx.x;                   // 0..31
    const int h0   = (tile >> 2) * TILE_H;
    const int w0   = (tile & 3) * TILE_W;
    const int co0  = cog * CO_PER_BLK;

    // Load weights ONCE: ws[(cin*9 + k)*32 + co_local]  (co fastest)
    #pragma unroll 4
    for (int i = tid; i < CIN * 9 * CO_PER_BLK; i += 128) {
        int col = i & 31;          // co local
        int k9  = i >> 5;          // cin*9 + kh*3 + kw
        ws[i] = Wt[(co0 + col) * (CIN * 9) + k9];
    }

    // Async halo fill for timestep t into buffer buf
    auto fill_halo = [&](int t, int buf) {
        const float* xt = x + (size_t)t * (CIN * PLANE);
        #pragma unroll 4
        for (int i = tid; i < XS_ELEMS; i += 128) {
            int c   = i % XS_WD;
            int rc  = i / XS_WD;
            int r   = rc % XS_H;
            int cin = rc / XS_H;
            int y   = h0 - 1 + r;
            int xg  = w0 - 1 + c;
            bool ok = ((unsigned)y < (unsigned)H) & ((unsigned)xg < (unsigned)W);
            const float* src = ok ? &xt[cin * PLANE + y * W + xg] : xt;
            uint32_t dst = (uint32_t)__cvta_generic_to_shared(
                &xs[buf][cin * (XS_H * XS_STRIDE) + r * XS_STRIDE + c]);
            cp_async4(dst, src, ok);
        }
        cp_async_commit();
    };

    // Prologue: halo for t0 into buffer 0
    fill_halo(t0, 0);

    const int co_sub = tid >> 5;            // 0..3  (uniform within warp)
    const int lane   = tid & 31;
    const int hl     = lane >> 2;           // 0..7
    const int wl     = (lane & 3) * 4;      // 0,4,8,12
    const int co_b   = co_sub * 8;          // local co base (8 c_out / thread)

    // bias pairs (reused across timesteps)
    uint64_t bp[4];
    #pragma unroll
    for (int p = 0; p < 4; p++)
        bp[p] = pk2(b[co0 + co_b + 2 * p], b[co0 + co_b + 2 * p + 1]);

    cp_async_wait_all();
    __syncthreads();

    #pragma unroll 1
    for (int tq = 0; tq < T_PER_BLK; tq++) {
        const int t   = t0 + tq;
        const int buf = tq & 1;

        // Prefetch next halo into idle buffer (async; overlaps compute)
        if (tq + 1 < T_PER_BLK) fill_halo(t + 1, 1 - buf);

        // acc[p][w] packs c_out pair (co_b+2p, co_b+2p+1) at output column w
        uint64_t acc[4][4];
        #pragma unroll
        for (int p = 0; p < 4; p++)
            #pragma unroll
            for (int w = 0; w < 4; w++) acc[p][w] = bp[p];

        #pragma unroll
        for (int cin = 0; cin < CIN; cin++) {
            #pragma unroll
            for (int kh = 0; kh < 3; kh++) {
                const float* row =
                    &xs[buf][cin * (XS_H * XS_STRIDE) + (hl + kh) * XS_STRIDE + wl];
                uint64_t xx[6];
                #pragma unroll
                for (int j = 0; j < 6; j++) {
                    float xv = row[j];
                    xx[j] = pk2(xv, xv);
                }
                const float* wp = &ws[(cin * 9 + kh * 3) * CO_PER_BLK + co_b];
                #pragma unroll
                for (int kw = 0; kw < 3; kw++) {
                    // 4 co-pairs for this kw: 32 contiguous bytes -> 2 LDS.128
                    ulonglong2 wlo =
                        *(const ulonglong2*)(wp + kw * CO_PER_BLK);
                    ulonglong2 whi =
                        *(const ulonglong2*)(wp + kw * CO_PER_BLK + 4);
                    uint64_t wk[4] = {wlo.x, wlo.y, whi.x, whi.y};
                    #pragma unroll
                    for (int p = 0; p < 4; p++) {
                        // 4 consecutive FFMA2 share b-operand wk[p] (.reuse)
                        #pragma unroll
                        for (int w = 0; w < 4; w++)
                            acc[p][w] = fma2(xx[w + kw], wk[p], acc[p][w]);
                    }
                }
            }
        }

        // Unpack and store: one float4 per c_out (w-contiguous, 16B aligned)
        #pragma unroll
        for (int p = 0; p < 4; p++) {
            float lo[4], hi[4];
            #pragma unroll
            for (int w = 0; w < 4; w++) upk2(acc[p][w], lo[w], hi[w]);
            int co_e = co0 + co_b + 2 * p;
            size_t base = (size_t)t * FRAME + (h0 + hl) * W + (w0 + wl);
            *(float4*)&g_conv[base + (size_t)co_e * PLANE] =
                make_float4(lo[0], lo[1], lo[2], lo[3]);
            *(float4*)&g_conv[base + (size_t)(co_e + 1) * PLANE] =
                make_float4(hi[0], hi[1], hi[2], hi[3]);
        }

        // Next buffer complete + everyone done reading current buffer
        cp_async_wait_all();
        __syncthreads();
    }
}

// ---------------------------------------------------------------------------
// Scan kernel: one thread per (c_out,h,w); sequential LIF over T.
// Proven best form: 256 threads, scalar coalesced loads (~38us, 71% DRAM).
// ---------------------------------------------------------------------------
__global__ __launch_bounds__(256)
void scan_kernel(float* __restrict__ out) {
    const int idx = blockIdx.x * 256 + threadIdx.x;   // < FRAME
    const float* cp = g_conv + idx;
    float* op = out + idx;
    float state = 0.0f;
    #pragma unroll 8
    for (int t = 0; t < T_STEPS; t++) {
        float v = cp[(size_t)t * FRAME];
        state += v;
        float spike = (state >= 8.0f) ? 1.0f : 0.0f;      // fire
        state = (state >= 8.0f) ? 0.0f : state;           // reset-to-value 0
        state = (state > -1.0f) ? state : -1.0f;          // Threshold(-1,-1)
        op[(size_t)t * FRAME] = spike;
    }
}

extern "C" void kernel_launch(void* const* d_in, const int* in_sizes, int n_in,
                              void* d_out, int out_size) {
    // Identify inputs by unique element counts (robust to ordering)
    const float* x  = nullptr;
    const float* Wt = nullptr;
    const float* b  = nullptr;
    for (int i = 0; i < n_in; i++) {
        if (in_sizes[i] == T_STEPS * CIN * PLANE) x  = (const float*)d_in[i];
        else if (in_sizes[i] == CO * CIN * 9)     Wt = (const float*)d_in[i];
        else if (in_sizes[i] == CO)               b  = (const float*)d_in[i];
    }
    float* out = (float*)d_out;

    dim3 grid(32, 2, T_STEPS / T_PER_BLK);      // 32 x 2 x 32 = 2048 blocks
    conv_kernel<<<grid, 128>>>(x, Wt, b);
    scan_kernel<<<FRAME / 256, 256>>>(out);
}